// round 4
// baseline (speedup 1.0000x reference)
#include <cuda_runtime.h>
#include <cstdint>

#define BB 2
#define CC 64
#define CQ 16
#define DD 96
#define PP 9216                    // H*W
#define PDSTRIDE (PP*DD)           // per-channel stride in x
#define CPD (CC*PDSTRIDE)          // per-batch stride in x
#define PCHUNK 32
#define PCOUT 16

typedef unsigned long long u64;

__device__ double g_energy[BB*DD*DD];
__device__ float  g_attn[BB*DD*DD];

// ---- packed f32x2 helpers (FFMA2 path only reachable via PTX) ----
__device__ __forceinline__ u64 pk2(float lo, float hi) {
    u64 r; asm("mov.b64 %0, {%1, %2};" : "=l"(r) : "f"(lo), "f"(hi)); return r;
}
__device__ __forceinline__ u64 bc2(float v) { return pk2(v, v); }
__device__ __forceinline__ void up2(float& lo, float& hi, u64 v) {
    asm("mov.b64 {%0, %1}, %2;" : "=f"(lo), "=f"(hi) : "l"(v));
}
__device__ __forceinline__ u64 ffma2(u64 a, u64 b, u64 c) {
    u64 d; asm("fma.rn.f32x2 %0, %1, %2, %3;" : "=l"(d) : "l"(a), "l"(b), "l"(c));
    return d;
}

// ---- cp.async helpers ----
__device__ __forceinline__ void cpa16(uint32_t dst, const float* src) {
    asm volatile("cp.async.cg.shared.global [%0], [%1], 16;" :: "r"(dst), "l"(src));
}
#define CP_COMMIT() asm volatile("cp.async.commit_group;" ::: "memory")
#define CP_WAIT0()  asm volatile("cp.async.wait_group 0;" ::: "memory")

// ===========================================================================
// Kernel A: energy[b,d,e] = sum_{p,cq} (Wq X_p + bq)[cq,d] * (Wk X_p + bk)[cq,e]
// Broadcast operands (Wq,Wk,Q) pre-duplicated in SMEM; X double-buffered via
// cp.async; 6d x 3 e-pair register tile, flushed once via fp64 atomics.
// ===========================================================================
#define E_WQD 0
#define E_WKD (E_WQD + CQ*CC*8)
#define E_QD  (E_WKD + CQ*CC*8)
#define E_K   (E_QD  + CQ*DD*8)
#define E_X0  (E_K   + CQ*DD*4)
#define E_TOTAL (E_X0 + 2*CC*DD*4)          // 83968 bytes

__global__ void __launch_bounds__(256, 2) energy_k(
    const float* __restrict__ x,
    const float* __restrict__ Wq, const float* __restrict__ bq,
    const float* __restrict__ Wk, const float* __restrict__ bk)
{
    extern __shared__ __align__(16) unsigned char esm[];
    u64*   sWqd = (u64*)(esm + E_WQD);
    u64*   sWkd = (u64*)(esm + E_WKD);
    u64*   sQd  = (u64*)(esm + E_QD);
    float* sK   = (float*)(esm + E_K);
    float* sXb[2] = { (float*)(esm + E_X0), (float*)(esm + E_X0 + CC*DD*4) };
    const uint32_t sXs[2] = {
        (uint32_t)__cvta_generic_to_shared(sXb[0]),
        (uint32_t)__cvta_generic_to_shared(sXb[1]) };

    const int t  = threadIdx.x;
    const int b  = blockIdx.y;
    const int p0 = blockIdx.x * PCHUNK;

    for (int i = t; i < CQ*CC; i += 256) {
        float wq = Wq[i], wk = Wk[i];
        sWqd[i] = pk2(wq, wq);
        sWkd[i] = pk2(wk, wk);
    }

    // QK-compute mapping: 1 cq x 6 consecutive d per thread
    const int cqi = t >> 4;            // 0..15
    const int dxb = 6 * (t & 15);      // d in [dxb, dxb+6)
    const u64 bqb = bc2(bq[cqi]);
    const u64 bkb = bc2(bk[cqi]);

    // accumulate mapping: d = tx+16i (scalar), e = 6*ty + 2j (pairs)
    const int tx = t & 15;
    const int ty = t >> 4;

    u64 acc[6][3];
    #pragma unroll
    for (int i = 0; i < 6; ++i)
        #pragma unroll
        for (int j = 0; j < 3; ++j) acc[i][j] = 0ull;

    const float* xb = x + (size_t)b * CPD;

    // prefetch first X slab (64x96 floats, 16B chunks: 1536/256 = 6 per thread)
    {
        const float* xp = xb + (size_t)p0 * DD;
        #pragma unroll
        for (int r = 0; r < 6; ++r) {
            int i = t + r*256;
            int c = i / 24, ch = i % 24;
            cpa16(sXs[0] + (uint32_t)(c*DD + ch*4)*4, xp + (size_t)c * PDSTRIDE + ch*4);
        }
        CP_COMMIT();
    }

    for (int pp = 0; pp < PCHUNK; ++pp) {
        CP_WAIT0();
        __syncthreads();          // X[pp] visible; prev accum done

        if (pp + 1 < PCHUNK) {
            const float* xp = xb + (size_t)(p0 + pp + 1) * DD;
            const uint32_t dbase = sXs[(pp + 1) & 1];
            #pragma unroll
            for (int r = 0; r < 6; ++r) {
                int i = t + r*256;
                int c = i / 24, ch = i % 24;
                cpa16(dbase + (uint32_t)(c*DD + ch*4)*4, xp + (size_t)c * PDSTRIDE + ch*4);
            }
            CP_COMMIT();
        }

        const float* sX = sXb[pp & 1];

        // ---- Q,K = W X + b  (1 cq x 3 d-pairs per thread) ----
        u64 qa[3], ka[3];
        #pragma unroll
        for (int j = 0; j < 3; ++j) { qa[j] = bqb; ka[j] = bkb; }

        #pragma unroll 4
        for (int c = 0; c < CC; ++c) {
            const u64 wqb = sWqd[cqi*CC + c];
            const u64 wkb = sWkd[cqi*CC + c];
            u64 xv[3];
            #pragma unroll
            for (int j = 0; j < 3; ++j)
                xv[j] = *reinterpret_cast<const u64*>(&sX[c*DD + dxb + 2*j]);
            #pragma unroll
            for (int j = 0; j < 3; ++j) {
                qa[j] = ffma2(wqb, xv[j], qa[j]);
                ka[j] = ffma2(wkb, xv[j], ka[j]);
            }
        }
        #pragma unroll
        for (int j = 0; j < 3; ++j) {
            float qlo, qhi; up2(qlo, qhi, qa[j]);
            float4 qd; qd.x = qlo; qd.y = qlo; qd.z = qhi; qd.w = qhi;
            *reinterpret_cast<float4*>(&sQd[cqi*DD + dxb + 2*j]) = qd;   // duplicated
            *reinterpret_cast<u64*>(&sK[cqi*DD + dxb + 2*j]) = ka[j];    // packed
        }
        __syncthreads();

        // ---- energy partial: acc[d, e-pair] += Q[cq,d] * K[cq, e-pair] ----
        #pragma unroll 2
        for (int cq = 0; cq < CQ; ++cq) {
            u64 kv[3];
            #pragma unroll
            for (int j = 0; j < 3; ++j)
                kv[j] = *reinterpret_cast<const u64*>(&sK[cq*DD + 6*ty + 2*j]);
            #pragma unroll
            for (int i = 0; i < 6; ++i) {
                const u64 qb = sQd[cq*DD + tx + 16*i];    // pre-duplicated
                #pragma unroll
                for (int j = 0; j < 3; ++j)
                    acc[i][j] = ffma2(qb, kv[j], acc[i][j]);
            }
        }
    }

    const size_t eb = (size_t)b * DD * DD;
    #pragma unroll
    for (int i = 0; i < 6; ++i)
        #pragma unroll
        for (int j = 0; j < 3; ++j) {
            float lo, hi;
            up2(lo, hi, acc[i][j]);
            const size_t base = eb + (size_t)(tx + 16*i)*DD + (6*ty + 2*j);
            atomicAdd(&g_energy[base],     (double)lo);
            atomicAdd(&g_energy[base + 1], (double)hi);
        }
}

// ===========================================================================
// Kernel B: row softmax over e. One warp per (b,d) row.
// ===========================================================================
__global__ void __launch_bounds__(128) softmax_k()
{
    const int w    = (blockIdx.x * blockDim.x + threadIdx.x) >> 5;
    const int lane = threadIdx.x & 31;
    if (w >= BB*DD) return;

    const double* er = g_energy + (size_t)w * DD;
    float v0 = (float)er[lane];
    float v1 = (float)er[lane + 32];
    float v2 = (float)er[lane + 64];

    float m = fmaxf(v0, fmaxf(v1, v2));
    #pragma unroll
    for (int o = 16; o > 0; o >>= 1) m = fmaxf(m, __shfl_xor_sync(0xffffffffu, m, o));

    float e0 = expf(v0 - m), e1 = expf(v1 - m), e2 = expf(v2 - m);
    float s = e0 + e1 + e2;
    #pragma unroll
    for (int o = 16; o > 0; o >>= 1) s += __shfl_xor_sync(0xffffffffu, s, o);

    const float inv = 1.0f / s;
    float* ar = g_attn + (size_t)w * DD;
    ar[lane]      = e0 * inv;
    ar[lane + 32] = e1 * inv;
    ar[lane + 64] = e2 * inv;
}

// ===========================================================================
// Kernel C: out[b,c,p,d] = gamma*( sum_e (Wv X_p + bv)[c,e] * attn[b,d,e] ) + x
// Wv and V pre-duplicated in SMEM; attn transposed (stride 98) so d-pairs are
// contiguous; X double-buffered via cp.async. 1 CTA/SM.
// ===========================================================================
#define ATS 98
#define O_WVD 0
#define O_AT  (O_WVD + CC*CC*8)                 // 32768
#define O_VD  (O_AT  + DD*ATS*4)                // 70400
#define O_X0  (O_VD  + CC*DD*8)                 // 119552
#define O_TOTAL (O_X0 + 2*CC*DD*4)              // 168704 bytes

__global__ void __launch_bounds__(256) out_k(
    const float* __restrict__ x, const float* __restrict__ Wv,
    const float* __restrict__ bv, const float* __restrict__ gamma,
    float* __restrict__ out)
{
    extern __shared__ __align__(16) unsigned char osm[];
    u64*   sWvd = (u64*)(osm + O_WVD);
    float* sAT  = (float*)(osm + O_AT);         // sAT[e*98 + d]
    u64*   sVd  = (u64*)(osm + O_VD);           // duplicated V[c][e]
    float* sXb[2] = { (float*)(osm + O_X0), (float*)(osm + O_X0 + CC*DD*4) };
    const uint32_t sXs[2] = {
        (uint32_t)__cvta_generic_to_shared(sXb[0]),
        (uint32_t)__cvta_generic_to_shared(sXb[1]) };

    const int t  = threadIdx.x;
    const int b  = blockIdx.y;
    const int p0 = blockIdx.x * PCOUT;
    const int tx = t & 15;                 // d-group: d = 6*tx + {0..5}
    const int ty = t >> 4;                 // c-group: c = 4*ty + {0..3}
    const int dxb = 6 * tx;

    for (int i = t; i < CC*CC; i += 256) {
        float w = Wv[i];
        sWvd[i] = pk2(w, w);
    }
    for (int i = t; i < DD*DD; i += 256) {
        int d = i / DD, e = i - d*DD;      // coalesced read of g_attn[b][d][e]
        sAT[e*ATS + d] = g_attn[(size_t)b*DD*DD + i];
    }
    const u64 gbc = bc2(gamma[0]);
    u64 bvb[4];
    #pragma unroll
    for (int k = 0; k < 4; ++k) bvb[k] = bc2(bv[4*ty + k]);

    const float* xb = x   + (size_t)b * CPD;
    float*       ob = out + (size_t)b * CPD;

    // prefetch first X slab
    {
        const float* xp = xb + (size_t)p0 * DD;
        #pragma unroll
        for (int r = 0; r < 6; ++r) {
            int i = t + r*256;
            int c = i / 24, ch = i % 24;
            cpa16(sXs[0] + (uint32_t)(c*DD + ch*4)*4, xp + (size_t)c * PDSTRIDE + ch*4);
        }
        CP_COMMIT();
    }

    for (int pp = 0; pp < PCOUT; ++pp) {
        const int p = p0 + pp;
        CP_WAIT0();
        __syncthreads();

        if (pp + 1 < PCOUT) {
            const float* xp = xb + (size_t)(p + 1) * DD;
            const uint32_t dbase = sXs[(pp + 1) & 1];
            #pragma unroll
            for (int r = 0; r < 6; ++r) {
                int i = t + r*256;
                int c = i / 24, ch = i % 24;
                cpa16(dbase + (uint32_t)(c*DD + ch*4)*4, xp + (size_t)c * PDSTRIDE + ch*4);
            }
            CP_COMMIT();
        }

        const float* sX = sXb[pp & 1];

        // ---- V = Wv X + bv  (4 c x 3 e-pairs per thread), 2-c2 batching ----
        u64 vv[4][3];
        #pragma unroll
        for (int k = 0; k < 4; ++k)
            #pragma unroll
            for (int j = 0; j < 3; ++j) vv[k][j] = bvb[k];

        #pragma unroll 2
        for (int c2 = 0; c2 < CC; c2 += 2) {
            u64 x0[3], x1[3];
            #pragma unroll
            for (int j = 0; j < 3; ++j) {
                x0[j] = *reinterpret_cast<const u64*>(&sX[c2*DD + dxb + 2*j]);
                x1[j] = *reinterpret_cast<const u64*>(&sX[(c2+1)*DD + dxb + 2*j]);
            }
            #pragma unroll
            for (int k = 0; k < 4; ++k) {
                const u64 wb0 = sWvd[(4*ty + k)*CC + c2];       // pre-duplicated
                const u64 wb1 = sWvd[(4*ty + k)*CC + c2 + 1];
                #pragma unroll
                for (int j = 0; j < 3; ++j) {
                    vv[k][j] = ffma2(wb0, x0[j], vv[k][j]);
                    vv[k][j] = ffma2(wb1, x1[j], vv[k][j]);
                }
            }
        }
        // store V duplicated: sVd[c][e] = (V,V)
        #pragma unroll
        for (int k = 0; k < 4; ++k)
            #pragma unroll
            for (int j = 0; j < 3; ++j) {
                float vlo, vhi; up2(vlo, vhi, vv[k][j]);
                float4 vd; vd.x = vlo; vd.y = vlo; vd.z = vhi; vd.w = vhi;
                *reinterpret_cast<float4*>(&sVd[(4*ty + k)*DD + dxb + 2*j]) = vd;
            }
        __syncthreads();

        // ---- out tile = V A^T  (4 c x 3 d-pairs per thread), 2-e batching ----
        u64 acc[4][3];
        #pragma unroll
        for (int k = 0; k < 4; ++k)
            #pragma unroll
            for (int j = 0; j < 3; ++j) acc[k][j] = 0ull;

        #pragma unroll 2
        for (int e = 0; e < DD; e += 2) {
            u64 a0[3], a1[3];
            #pragma unroll
            for (int j = 0; j < 3; ++j) {
                a0[j] = *reinterpret_cast<const u64*>(&sAT[e*ATS + dxb + 2*j]);
                a1[j] = *reinterpret_cast<const u64*>(&sAT[(e+1)*ATS + dxb + 2*j]);
            }
            #pragma unroll
            for (int k = 0; k < 4; ++k) {
                const u64 vb0 = sVd[(4*ty + k)*DD + e];         // pre-duplicated
                const u64 vb1 = sVd[(4*ty + k)*DD + e + 1];
                #pragma unroll
                for (int j = 0; j < 3; ++j) {
                    acc[k][j] = ffma2(vb0, a0[j], acc[k][j]);
                    acc[k][j] = ffma2(vb1, a1[j], acc[k][j]);
                }
            }
        }

        // ---- epilogue: out = gamma*acc + x, packed stores ----
        #pragma unroll
        for (int k = 0; k < 4; ++k) {
            const int c = 4*ty + k;
            #pragma unroll
            for (int j = 0; j < 3; ++j) {
                const u64 x2 = *reinterpret_cast<const u64*>(&sX[c*DD + dxb + 2*j]);
                const u64 r  = ffma2(acc[k][j], gbc, x2);
                *reinterpret_cast<u64*>(&ob[(size_t)c * PDSTRIDE + (size_t)p * DD + dxb + 2*j]) = r;
            }
        }
    }
}

// ---------------------------------------------------------------------------
extern "C" void kernel_launch(void* const* d_in, const int* in_sizes, int n_in,
                              void* d_out, int out_size)
{
    const float* x  = (const float*)d_in[0];
    const float* Wq = (const float*)d_in[1];
    const float* bq = (const float*)d_in[2];
    const float* Wk = (const float*)d_in[3];
    const float* bk = (const float*)d_in[4];
    const float* Wv = (const float*)d_in[5];
    const float* bv = (const float*)d_in[6];
    const float* gm = (const float*)d_in[7];
    float* out = (float*)d_out;

    void* eptr = nullptr;
    cudaGetSymbolAddress(&eptr, g_energy);
    cudaMemsetAsync(eptr, 0, sizeof(double)*BB*DD*DD, 0);

    cudaFuncSetAttribute(energy_k, cudaFuncAttributeMaxDynamicSharedMemorySize, E_TOTAL);
    energy_k<<<dim3(PP/PCHUNK, BB), 256, E_TOTAL>>>(x, Wq, bq, Wk, bk);

    softmax_k<<<(BB*DD*32 + 127)/128, 128>>>();

    cudaFuncSetAttribute(out_k, cudaFuncAttributeMaxDynamicSharedMemorySize, O_TOTAL);
    out_k<<<dim3(PP/PCOUT, BB), 256, O_TOTAL>>>(x, Wv, bv, gm, out);
}

// round 5
// speedup vs baseline: 1.0249x; 1.0249x over previous
#include <cuda_runtime.h>
#include <cstdint>

#define BB 2
#define CC 64
#define CQ 16
#define DD 96
#define PP 9216                    // H*W
#define PDSTRIDE (PP*DD)           // per-channel stride in x
#define CPD (CC*PDSTRIDE)          // per-batch stride in x
#define PCHUNK 32
#define PCOUT 16

typedef unsigned long long u64;

__device__ double g_energy[BB*DD*DD];
__device__ float  g_attn[BB*DD*DD];

// ---- packed f32x2 helpers (FFMA2 path only reachable via PTX) ----
__device__ __forceinline__ u64 pk2(float lo, float hi) {
    u64 r; asm("mov.b64 %0, {%1, %2};" : "=l"(r) : "f"(lo), "f"(hi)); return r;
}
__device__ __forceinline__ u64 bc2(float v) { return pk2(v, v); }
__device__ __forceinline__ void up2(float& lo, float& hi, u64 v) {
    asm("mov.b64 {%0, %1}, %2;" : "=f"(lo), "=f"(hi) : "l"(v));
}
__device__ __forceinline__ u64 ffma2(u64 a, u64 b, u64 c) {
    u64 d; asm("fma.rn.f32x2 %0, %1, %2, %3;" : "=l"(d) : "l"(a), "l"(b), "l"(c));
    return d;
}

// ===========================================================================
// Kernel A: energy[b,d,e] = sum_{p,cq} (Wq X_p + bq)[cq,d] * (Wk X_p + bk)[cq,e]
// Single-barrier pipeline: X and Q/K double-buffered; LDG of X(p+2) in regs
// overlaps accum(p) and QK(p+1). Inner loops identical to R3.
// ===========================================================================
#define E_W   0
#define E_X0  (E_W  + 2*CQ*CC*4)                 // 8192
#define E_Q0  (E_X0 + 2*CC*DD*4)                 // 57344
#define E_K0  (E_Q0 + 2*CQ*DD*4)                 // 69632
#define E_TOTAL (E_K0 + 2*CQ*DD*4)               // 81920 bytes

__global__ void __launch_bounds__(256, 2) energy_k(
    const float* __restrict__ x,
    const float* __restrict__ Wq, const float* __restrict__ bq,
    const float* __restrict__ Wk, const float* __restrict__ bk)
{
    extern __shared__ __align__(16) unsigned char esm[];
    float* sWq = (float*)(esm + E_W);
    float* sWk = sWq + CQ*CC;
    float* sXb[2] = { (float*)(esm + E_X0), (float*)(esm + E_X0) + CC*DD };
    float* sQb[2] = { (float*)(esm + E_Q0), (float*)(esm + E_Q0) + CQ*DD };
    float* sKb[2] = { (float*)(esm + E_K0), (float*)(esm + E_K0) + CQ*DD };

    const int t  = threadIdx.x;
    const int b  = blockIdx.y;
    const int p0 = blockIdx.x * PCHUNK;

    for (int i = t; i < CQ*CC; i += 256) {
        sWq[i] = Wq[i];
        sWk[i] = Wk[i];
    }

    // QK-compute mapping: 1 cq x 6 consecutive d per thread
    const int cqi = t >> 4;
    const int dxb = 6 * (t & 15);
    const float bq_s = bq[cqi];
    const float bk_s = bk[cqi];

    // accumulate mapping: d = tx+16i (scalar), e = 6*ty + 2j (pairs)
    const int tx = t & 15;
    const int ty = t >> 4;

    u64 acc[6][3];
    #pragma unroll
    for (int i = 0; i < 6; ++i)
        #pragma unroll
        for (int j = 0; j < 3; ++j) acc[i][j] = 0ull;

    const float* xb = x + (size_t)b * CPD;
    const int lc = t / 48, ldp = t % 48;      // slab load coords (base)

    float2 r[12];
    // helpers inline: slab(p) -> r ; r -> sX[buf]
    #define LDG_SLAB(P)  {                                                      \
        const float* xp = xb + (size_t)(P) * DD;                                \
        _Pragma("unroll")                                                       \
        for (int rr = 0; rr < 12; ++rr) {                                       \
            int i2 = t + rr*256;                                                \
            int c = i2 / 48, dp = i2 % 48;                                      \
            r[rr] = *reinterpret_cast<const float2*>(xp + (size_t)c * PDSTRIDE + 2*dp); } }
    #define STS_SLAB(BUF) {                                                     \
        _Pragma("unroll")                                                       \
        for (int rr = 0; rr < 12; ++rr) {                                       \
            int i2 = t + rr*256;                                                \
            int c = i2 / 48, dp = i2 % 48;                                      \
            *reinterpret_cast<float2*>(&(BUF)[c*DD + 2*dp]) = r[rr]; } }

    // ---- QK compute (identical math to R3), from sX buf into sQ/sK buf ----
    #define QK_COMPUTE(SXP, SQP, SKP) {                                         \
        u64 qa[3], ka[3];                                                       \
        _Pragma("unroll")                                                       \
        for (int j = 0; j < 3; ++j) { qa[j] = bc2(bq_s); ka[j] = bc2(bk_s); }   \
        _Pragma("unroll 4")                                                     \
        for (int c4 = 0; c4 < CC; c4 += 4) {                                    \
            const float4 wq4 = *reinterpret_cast<const float4*>(&sWq[cqi*CC + c4]); \
            const float4 wk4 = *reinterpret_cast<const float4*>(&sWk[cqi*CC + c4]); \
            const float wqa[4] = {wq4.x, wq4.y, wq4.z, wq4.w};                  \
            const float wka[4] = {wk4.x, wk4.y, wk4.z, wk4.w};                  \
            _Pragma("unroll")                                                   \
            for (int cc = 0; cc < 4; ++cc) {                                    \
                const int c = c4 + cc;                                          \
                u64 xv[3];                                                      \
                _Pragma("unroll")                                               \
                for (int j = 0; j < 3; ++j)                                     \
                    xv[j] = *reinterpret_cast<const u64*>(&(SXP)[c*DD + dxb + 2*j]); \
                const u64 wqb = bc2(wqa[cc]);                                   \
                const u64 wkb = bc2(wka[cc]);                                   \
                _Pragma("unroll")                                               \
                for (int j = 0; j < 3; ++j) {                                   \
                    qa[j] = ffma2(wqb, xv[j], qa[j]);                           \
                    ka[j] = ffma2(wkb, xv[j], ka[j]);                           \
                } } }                                                           \
        _Pragma("unroll")                                                       \
        for (int j = 0; j < 3; ++j) {                                           \
            *reinterpret_cast<u64*>(&(SQP)[cqi*DD + dxb + 2*j]) = qa[j];        \
            *reinterpret_cast<u64*>(&(SKP)[cqi*DD + dxb + 2*j]) = ka[j];        \
        } }

    // ---- prologue ----
    LDG_SLAB(p0);
    STS_SLAB(sXb[0]);
    __syncthreads();                       // W + X0 visible
    QK_COMPUTE(sXb[0], sQb[0], sKb[0]);
    LDG_SLAB(p0 + 1);
    STS_SLAB(sXb[1]);
    __syncthreads();                       // QK0 + X1 visible

    // ---- main loop: one barrier per p ----
    for (int pp = 0; pp < PCHUNK; ++pp) {
        if (pp + 2 < PCHUNK) LDG_SLAB(p0 + pp + 2);

        if (pp + 1 < PCHUNK) {
            float* sxn = sXb[(pp + 1) & 1];
            float* sqn = sQb[(pp + 1) & 1];
            float* skn = sKb[(pp + 1) & 1];
            QK_COMPUTE(sxn, sqn, skn);
        }

        // ---- accum(pp): identical to R3 ----
        {
            const float* sQ = sQb[pp & 1];
            const float* sK = sKb[pp & 1];
            #pragma unroll 2
            for (int cq = 0; cq < CQ; ++cq) {
                u64 kv[3];
                #pragma unroll
                for (int j = 0; j < 3; ++j)
                    kv[j] = *reinterpret_cast<const u64*>(&sK[cq*DD + 6*ty + 2*j]);
                #pragma unroll
                for (int i = 0; i < 6; ++i) {
                    const u64 qb = bc2(sQ[cq*DD + tx + 16*i]);
                    #pragma unroll
                    for (int j = 0; j < 3; ++j)
                        acc[i][j] = ffma2(qb, kv[j], acc[i][j]);
                }
            }
        }

        if (pp + 2 < PCHUNK) STS_SLAB(sXb[pp & 1]);
        __syncthreads();
    }

    const size_t eb = (size_t)b * DD * DD;
    #pragma unroll
    for (int i = 0; i < 6; ++i)
        #pragma unroll
        for (int j = 0; j < 3; ++j) {
            float lo, hi;
            up2(lo, hi, acc[i][j]);
            const size_t base = eb + (size_t)(tx + 16*i)*DD + (6*ty + 2*j);
            atomicAdd(&g_energy[base],     (double)lo);
            atomicAdd(&g_energy[base + 1], (double)hi);
        }
    #undef LDG_SLAB
    #undef STS_SLAB
    #undef QK_COMPUTE
}

// ===========================================================================
// Kernel B: row softmax over e. One warp per (b,d) row.
// ===========================================================================
__global__ void __launch_bounds__(128) softmax_k()
{
    const int w    = (blockIdx.x * blockDim.x + threadIdx.x) >> 5;
    const int lane = threadIdx.x & 31;
    if (w >= BB*DD) return;

    const double* er = g_energy + (size_t)w * DD;
    float v0 = (float)er[lane];
    float v1 = (float)er[lane + 32];
    float v2 = (float)er[lane + 64];

    float m = fmaxf(v0, fmaxf(v1, v2));
    #pragma unroll
    for (int o = 16; o > 0; o >>= 1) m = fmaxf(m, __shfl_xor_sync(0xffffffffu, m, o));

    float e0 = expf(v0 - m), e1 = expf(v1 - m), e2 = expf(v2 - m);
    float s = e0 + e1 + e2;
    #pragma unroll
    for (int o = 16; o > 0; o >>= 1) s += __shfl_xor_sync(0xffffffffu, s, o);

    const float inv = 1.0f / s;
    float* ar = g_attn + (size_t)w * DD;
    ar[lane]      = e0 * inv;
    ar[lane + 32] = e1 * inv;
    ar[lane + 64] = e2 * inv;
}

// ===========================================================================
// Kernel C: out[b,c,p,d] = gamma*( sum_e (Wv X_p + bv)[c,e] * attn[b,d,e] ) + x
// Single-barrier pipeline: X and V double-buffered; residual comes from a
// small early LDG (L1/L2-hot) so the epilogue never touches sX. 1 CTA/SM.
// Inner loops identical to R3.
// ===========================================================================
#define ATS 98
#define O_WV  0
#define O_AT  (O_WV + CC*CC*4)                   // 16384
#define O_X0  (O_AT + DD*ATS*4)                  // 54016
#define O_V0  (O_X0 + 2*CC*DD*4)                 // 103168
#define O_TOTAL (O_V0 + 2*CC*DD*4)               // 152320 bytes

__global__ void __launch_bounds__(256) out_k(
    const float* __restrict__ x, const float* __restrict__ Wv,
    const float* __restrict__ bv, const float* __restrict__ gamma,
    float* __restrict__ out)
{
    extern __shared__ __align__(16) unsigned char osm[];
    float* sWv = (float*)(osm + O_WV);
    float* sAT = (float*)(osm + O_AT);           // sAT[e*98 + d]
    float* sXb[2] = { (float*)(osm + O_X0), (float*)(osm + O_X0) + CC*DD };
    float* sVb[2] = { (float*)(osm + O_V0), (float*)(osm + O_V0) + CC*DD };

    const int t  = threadIdx.x;
    const int b  = blockIdx.y;
    const int p0 = blockIdx.x * PCOUT;
    const int tx = t & 15;                 // d-group: d = 6*tx + {0..5}
    const int ty = t >> 4;                 // c-group: c = 4*ty + {0..3}
    const int dxb = 6 * tx;

    for (int i = t; i < CC*CC; i += 256) sWv[i] = Wv[i];
    for (int i = t; i < DD*DD; i += 256) {
        int d = i / DD, e = i - d*DD;      // coalesced read of g_attn[b][d][e]
        sAT[e*ATS + d] = g_attn[(size_t)b*DD*DD + i];
    }
    const u64 gbc = bc2(gamma[0]);
    float bvv[4];
    #pragma unroll
    for (int k = 0; k < 4; ++k) bvv[k] = bv[4*ty + k];

    const float* xb = x   + (size_t)b * CPD;
    float*       ob = out + (size_t)b * CPD;

    float2 r[12];
    #define LDG_SLAB(P)  {                                                      \
        const float* xp = xb + (size_t)(P) * DD;                                \
        _Pragma("unroll")                                                       \
        for (int rr = 0; rr < 12; ++rr) {                                       \
            int i2 = t + rr*256;                                                \
            int c = i2 / 48, dp = i2 % 48;                                      \
            r[rr] = *reinterpret_cast<const float2*>(xp + (size_t)c * PDSTRIDE + 2*dp); } }
    #define STS_SLAB(BUF) {                                                     \
        _Pragma("unroll")                                                       \
        for (int rr = 0; rr < 12; ++rr) {                                       \
            int i2 = t + rr*256;                                                \
            int c = i2 / 48, dp = i2 % 48;                                      \
            *reinterpret_cast<float2*>(&(BUF)[c*DD + 2*dp]) = r[rr]; } }

    // ---- V = Wv X + bv (identical math to R3), sX buf -> sV buf ----
    #define V_COMPUTE(SXP, SVP) {                                               \
        u64 vv[4][3];                                                           \
        _Pragma("unroll")                                                       \
        for (int k = 0; k < 4; ++k)                                             \
            _Pragma("unroll")                                                   \
            for (int j = 0; j < 3; ++j) vv[k][j] = bc2(bvv[k]);                 \
        _Pragma("unroll 2")                                                     \
        for (int c2 = 0; c2 < CC; c2 += 2) {                                    \
            u64 x0[3], x1[3];                                                   \
            _Pragma("unroll")                                                   \
            for (int j = 0; j < 3; ++j) {                                       \
                x0[j] = *reinterpret_cast<const u64*>(&(SXP)[c2*DD + dxb + 2*j]);     \
                x1[j] = *reinterpret_cast<const u64*>(&(SXP)[(c2+1)*DD + dxb + 2*j]); \
            }                                                                   \
            _Pragma("unroll")                                                   \
            for (int k = 0; k < 4; ++k) {                                       \
                const u64 w2 = *reinterpret_cast<const u64*>(&sWv[(4*ty + k)*CC + c2]); \
                float wlo, whi; up2(wlo, whi, w2);                              \
                const u64 wb0 = bc2(wlo), wb1 = bc2(whi);                       \
                _Pragma("unroll")                                               \
                for (int j = 0; j < 3; ++j) {                                   \
                    vv[k][j] = ffma2(wb0, x0[j], vv[k][j]);                     \
                    vv[k][j] = ffma2(wb1, x1[j], vv[k][j]);                     \
                } } }                                                           \
        _Pragma("unroll")                                                       \
        for (int k = 0; k < 4; ++k)                                             \
            _Pragma("unroll")                                                   \
            for (int j = 0; j < 3; ++j)                                         \
                *reinterpret_cast<u64*>(&(SVP)[(4*ty + k)*DD + dxb + 2*j]) = vv[k][j]; }

    // ---- prologue ----
    LDG_SLAB(p0);
    STS_SLAB(sXb[0]);
    __syncthreads();                       // Wv, AT, X0 visible
    V_COMPUTE(sXb[0], sVb[0]);
    LDG_SLAB(p0 + 1);
    STS_SLAB(sXb[1]);
    __syncthreads();                       // V0 + X1 visible

    // ---- main loop: one barrier per p ----
    for (int pp = 0; pp < PCOUT; ++pp) {
        const int p = p0 + pp;

        // residual tile: early LDG, L1/L2-hot (slab read ~2 iters ago)
        u64 res[4][3];
        {
            const float* xp = xb + (size_t)p * DD;
            #pragma unroll
            for (int k = 0; k < 4; ++k)
                #pragma unroll
                for (int j = 0; j < 3; ++j)
                    res[k][j] = *reinterpret_cast<const u64*>(
                        xp + (size_t)(4*ty + k) * PDSTRIDE + dxb + 2*j);
        }

        if (pp + 2 < PCOUT) LDG_SLAB(p0 + pp + 2);

        if (pp + 1 < PCOUT) {
            float* sxn = sXb[(pp + 1) & 1];
            float* svn = sVb[(pp + 1) & 1];
            V_COMPUTE(sxn, svn);
        }

        // ---- accum(pp): identical to R3 ----
        u64 acc[4][3];
        #pragma unroll
        for (int k = 0; k < 4; ++k)
            #pragma unroll
            for (int j = 0; j < 3; ++j) acc[k][j] = 0ull;

        {
            const float* sV = sVb[pp & 1];
            #pragma unroll 2
            for (int e = 0; e < DD; e += 2) {
                u64 a0[3], a1[3];
                #pragma unroll
                for (int j = 0; j < 3; ++j) {
                    a0[j] = *reinterpret_cast<const u64*>(&sAT[e*ATS + dxb + 2*j]);
                    a1[j] = *reinterpret_cast<const u64*>(&sAT[(e+1)*ATS + dxb + 2*j]);
                }
                #pragma unroll
                for (int k = 0; k < 4; ++k) {
                    const u64 v2 = *reinterpret_cast<const u64*>(&sV[(4*ty + k)*DD + e]);
                    float vlo, vhi; up2(vlo, vhi, v2);
                    const u64 vb0 = bc2(vlo), vb1 = bc2(vhi);
                    #pragma unroll
                    for (int j = 0; j < 3; ++j) {
                        acc[k][j] = ffma2(vb0, a0[j], acc[k][j]);
                        acc[k][j] = ffma2(vb1, a1[j], acc[k][j]);
                    }
                }
            }
        }

        // ---- epilogue: out = gamma*acc + res (registers, not sX) ----
        #pragma unroll
        for (int k = 0; k < 4; ++k) {
            const int c = 4*ty + k;
            #pragma unroll
            for (int j = 0; j < 3; ++j) {
                const u64 o = ffma2(acc[k][j], gbc, res[k][j]);
                *reinterpret_cast<u64*>(&ob[(size_t)c * PDSTRIDE + (size_t)p * DD + dxb + 2*j]) = o;
            }
        }

        if (pp + 2 < PCOUT) STS_SLAB(sXb[pp & 1]);
        __syncthreads();
    }
    #undef LDG_SLAB
    #undef STS_SLAB
    #undef V_COMPUTE
}

// ---------------------------------------------------------------------------
extern "C" void kernel_launch(void* const* d_in, const int* in_sizes, int n_in,
                              void* d_out, int out_size)
{
    const float* x  = (const float*)d_in[0];
    const float* Wq = (const float*)d_in[1];
    const float* bq = (const float*)d_in[2];
    const float* Wk = (const float*)d_in[3];
    const float* bk = (const float*)d_in[4];
    const float* Wv = (const float*)d_in[5];
    const float* bv = (const float*)d_in[6];
    const float* gm = (const float*)d_in[7];
    float* out = (float*)d_out;

    void* eptr = nullptr;
    cudaGetSymbolAddress(&eptr, g_energy);
    cudaMemsetAsync(eptr, 0, sizeof(double)*BB*DD*DD, 0);

    cudaFuncSetAttribute(energy_k, cudaFuncAttributeMaxDynamicSharedMemorySize, E_TOTAL);
    energy_k<<<dim3(PP/PCHUNK, BB), 256, E_TOTAL>>>(x, Wq, bq, Wk, bk);

    softmax_k<<<(BB*DD*32 + 127)/128, 128>>>();

    cudaFuncSetAttribute(out_k, cudaFuncAttributeMaxDynamicSharedMemorySize, O_TOTAL);
    out_k<<<dim3(PP/PCOUT, BB), 256, O_TOTAL>>>(x, Wv, bv, gm, out);
}